// round 2
// baseline (speedup 1.0000x reference)
#include <cuda_runtime.h>
#include <cuda_bf16.h>
#include <math_constants.h>

// CircularBasisLayer: out[t, s*16+r] = rbf(D[id3[t]])[r] * gaussian_cbf(cos_phi[t])[s]
// E = 400000 edges, T = 2000000 triplets, R = 16, S = 8.
// NOTE: id3 is int32 (JAX without x64 downgrades jnp.int64 -> int32).
//
// Strategy:
//   Kernel 1: precompute rbf[E,16] (25.6 MB, L2-resident) with accurate sinf.
//   Kernel 2: one warp per triplet; lane l writes float4 at output offset 4l.
//             Fully coalesced 512B store per triplet -> HBM store-bound.

#define NUM_RADIAL 16
#define NUM_SPHERICAL 8
#define MAX_EDGES 400000

// scratch (no cudaMalloc allowed) — 25.6 MB
__device__ float g_rbf[(size_t)MAX_EDGES * NUM_RADIAL];

__global__ void rbf_precompute_kernel(const float* __restrict__ D, int E) {
    int e = blockIdx.x * blockDim.x + threadIdx.x;
    if (e >= E) return;
    float d = D[e];
    float ds = d * (1.0f / 6.0f);           // d_scaled = D / CUTOFF
    // envelope: 1 + a*ds^5 + b*ds^6 + c*ds^7, a=-21, b=35, c=-15
    float ds2 = ds * ds;
    float ds5 = ds2 * ds2 * ds;
    float env = 1.0f + ds5 * (-21.0f + ds * (35.0f - 15.0f * ds));
    if (ds >= 1.0f) env = 0.0f;
    const float norm = 0.09622504486493764f;  // sqrt(2 / 6^3)
    float pref = env * norm / d;
    float base = CUDART_PI_F * ds;

    float* outp = g_rbf + (size_t)e * NUM_RADIAL;
    float buf[NUM_RADIAL];
#pragma unroll
    for (int r = 0; r < NUM_RADIAL; r++) {
        buf[r] = pref * sinf((float)(r + 1) * base);
    }
#pragma unroll
    for (int q = 0; q < NUM_RADIAL / 4; q++) {
        reinterpret_cast<float4*>(outp)[q] =
            make_float4(buf[4 * q + 0], buf[4 * q + 1], buf[4 * q + 2], buf[4 * q + 3]);
    }
}

__global__ void triplet_outer_kernel(const float* __restrict__ cos_phi,
                                     const int* __restrict__ id3,
                                     float* __restrict__ out, int T) {
    int gwarp = (int)((blockIdx.x * (size_t)blockDim.x + threadIdx.x) >> 5);
    int lane = threadIdx.x & 31;
    if (gwarp >= T) return;

    int e = id3[gwarp];                // broadcast load (same addr across warp)
    float c = cos_phi[gwarp];          // broadcast load

    // lane l covers output floats [4l, 4l+4): s = l>>2 (fixed), r0 = (l&3)*4
    int s = lane >> 2;
    float offset = -1.0f + (float)s * (2.0f / 7.0f);   // linspace(-1,1,8)
    float diff = c - offset;
    float cbf = expf(-6.125f * diff * diff);            // coeff = -0.5/(2/7)^2

    const float4* rrow = reinterpret_cast<const float4*>(g_rbf + (size_t)e * NUM_RADIAL);
    float4 r4 = rrow[lane & 3];                         // 8 lanes share each 16B word

    float4 o = make_float4(r4.x * cbf, r4.y * cbf, r4.z * cbf, r4.w * cbf);
    reinterpret_cast<float4*>(out + (size_t)gwarp * (NUM_RADIAL * NUM_SPHERICAL))[lane] = o;
}

extern "C" void kernel_launch(void* const* d_in, const int* in_sizes, int n_in,
                              void* d_out, int out_size) {
    const float* D_ca    = (const float*)d_in[0];
    const float* cos_phi = (const float*)d_in[1];
    const int* id3_ca    = (const int*)d_in[2];
    float* out = (float*)d_out;

    int E = in_sizes[0];
    int T = in_sizes[1];

    {
        int threads = 256;
        int blocks = (E + threads - 1) / threads;
        rbf_precompute_kernel<<<blocks, threads>>>(D_ca, E);
    }
    {
        int threads = 256;                       // 8 warps = 8 triplets per block
        long long total_threads = (long long)T * 32;
        int blocks = (int)((total_threads + threads - 1) / threads);
        triplet_outer_kernel<<<blocks, threads>>>(cos_phi, id3_ca, out, T);
    }
}

// round 3
// speedup vs baseline: 1.8980x; 1.8980x over previous
#include <cuda_runtime.h>
#include <cuda_bf16.h>
#include <math_constants.h>

// CircularBasisLayer: out[t, s*16+r] = rbf(D[id3[t]])[r] * gaussian_cbf(cos_phi[t])[s]
// E = 400000, T = 2000000, R = 16, S = 8. id3 is int32.
//
// Kernel 1: precompute rbf[E,16] (25.6 MB, L2-resident), sincosf + recurrence.
// Kernel 2: one warp per 8 triplets; 8 independent gathers + 8 STG.128 in
//           flight per warp (fixes the latency-bound profile of round 2).

#define NUM_RADIAL 16
#define NUM_SPHERICAL 8
#define MAX_EDGES 400000
#define WPT 8   // triplets per warp

__device__ float g_rbf[(size_t)MAX_EDGES * NUM_RADIAL];

__global__ void rbf_precompute_kernel(const float* __restrict__ D, int E) {
    int e = blockIdx.x * blockDim.x + threadIdx.x;
    if (e >= E) return;
    float d = D[e];
    float ds = d * (1.0f / 6.0f);
    float ds2 = ds * ds;
    float ds5 = ds2 * ds2 * ds;
    float env = 1.0f + ds5 * (-21.0f + ds * (35.0f - 15.0f * ds));
    if (ds >= 1.0f) env = 0.0f;
    const float norm = 0.09622504486493764f;  // sqrt(2 / 6^3)
    float pref = env * norm / d;
    float x = CUDART_PI_F * ds;

    // sin(n*x) via Chebyshev recurrence: s_{n+1} = 2 cos(x) * s_n - s_{n-1}
    float s1, c1;
    sincosf(x, &s1, &c1);
    float twoc = 2.0f * c1;

    float buf[NUM_RADIAL];
    float sm1 = 0.0f;      // sin(0)
    float s0 = s1;         // sin(x)
    buf[0] = pref * s0;
#pragma unroll
    for (int r = 1; r < NUM_RADIAL; r++) {
        float sn = twoc * s0 - sm1;
        sm1 = s0;
        s0 = sn;
        buf[r] = pref * sn;
    }
    float* outp = g_rbf + (size_t)e * NUM_RADIAL;
#pragma unroll
    for (int q = 0; q < NUM_RADIAL / 4; q++) {
        reinterpret_cast<float4*>(outp)[q] =
            make_float4(buf[4 * q + 0], buf[4 * q + 1], buf[4 * q + 2], buf[4 * q + 3]);
    }
}

__device__ __forceinline__ void store_cs(float4* p, float4 v) {
    asm volatile("st.global.cs.v4.f32 [%0], {%1,%2,%3,%4};"
                 :: "l"(p), "f"(v.x), "f"(v.y), "f"(v.z), "f"(v.w) : "memory");
}

__global__ __launch_bounds__(256)
void triplet_outer_kernel(const float* __restrict__ cos_phi,
                          const int* __restrict__ id3,
                          float* __restrict__ out, int T) {
    size_t warpId = (blockIdx.x * (size_t)blockDim.x + threadIdx.x) >> 5;
    int lane = threadIdx.x & 31;
    size_t t0 = warpId * WPT;
    if (t0 >= (size_t)T) return;

    int s = lane >> 2;
    float offset = -1.0f + (float)s * (2.0f / 7.0f);
    int rq = lane & 3;

    if (t0 + WPT <= (size_t)T) {
        // lane-uniform vector loads: broadcast within warp
        int4 e0 = *reinterpret_cast<const int4*>(id3 + t0);
        int4 e1 = *reinterpret_cast<const int4*>(id3 + t0 + 4);
        float4 c0 = *reinterpret_cast<const float4*>(cos_phi + t0);
        float4 c1 = *reinterpret_cast<const float4*>(cos_phi + t0 + 4);
        int   e[WPT] = {e0.x, e0.y, e0.z, e0.w, e1.x, e1.y, e1.z, e1.w};
        float c[WPT] = {c0.x, c0.y, c0.z, c0.w, c1.x, c1.y, c1.z, c1.w};

        // 8 independent gathers in flight
        float4 r[WPT];
#pragma unroll
        for (int j = 0; j < WPT; j++)
            r[j] = reinterpret_cast<const float4*>(g_rbf + (size_t)e[j] * NUM_RADIAL)[rq];

        float cb[WPT];
#pragma unroll
        for (int j = 0; j < WPT; j++) {
            float df = c[j] - offset;
            cb[j] = __expf(-6.125f * df * df);
        }

#pragma unroll
        for (int j = 0; j < WPT; j++) {
            float4 o = make_float4(r[j].x * cb[j], r[j].y * cb[j],
                                   r[j].z * cb[j], r[j].w * cb[j]);
            store_cs(reinterpret_cast<float4*>(
                         out + (t0 + j) * (NUM_RADIAL * NUM_SPHERICAL)) + lane, o);
        }
    } else {
        // tail
        for (size_t t = t0; t < (size_t)T; t++) {
            int ee = id3[t];
            float cc = cos_phi[t];
            float df = cc - offset;
            float cb = __expf(-6.125f * df * df);
            float4 r4 = reinterpret_cast<const float4*>(g_rbf + (size_t)ee * NUM_RADIAL)[rq];
            float4 o = make_float4(r4.x * cb, r4.y * cb, r4.z * cb, r4.w * cb);
            store_cs(reinterpret_cast<float4*>(
                         out + t * (NUM_RADIAL * NUM_SPHERICAL)) + lane, o);
        }
    }
}

extern "C" void kernel_launch(void* const* d_in, const int* in_sizes, int n_in,
                              void* d_out, int out_size) {
    const float* D_ca    = (const float*)d_in[0];
    const float* cos_phi = (const float*)d_in[1];
    const int* id3_ca    = (const int*)d_in[2];
    float* out = (float*)d_out;

    int E = in_sizes[0];
    int T = in_sizes[1];

    {
        int threads = 256;
        int blocks = (E + threads - 1) / threads;
        rbf_precompute_kernel<<<blocks, threads>>>(D_ca, E);
    }
    {
        int threads = 256;  // 8 warps/block, 8 triplets/warp -> 64 triplets/block
        long long numWarps = ((long long)T + WPT - 1) / WPT;
        int blocks = (int)((numWarps * 32 + threads - 1) / threads);
        triplet_outer_kernel<<<blocks, threads>>>(cos_phi, id3_ca, out, T);
    }
}